// round 14
// baseline (speedup 1.0000x reference)
#include <cuda_runtime.h>
#include <cuda_fp16.h>
#include <cstdint>

#define NMAX 100000
#define HH   128
#define KS2  136          // padded row stride (half elems) for K=128 tiles

// Per-node projections (fp16). [node][256]: cols 0..127 = z@W1a (left/src),
// cols 128..255 = z@W1b + b1 (right/dst, bias folded).
__device__ __half g_P[(size_t)NMAX * 256];
__device__ __half g_O[(size_t)NMAX * 256];

// Pre-built B' image: [n(256 output cols)][KS2] fp16 (w1 transposed, fp16).
__device__ __align__(16) __half g_Bimg[256 * KS2];

// ---------------- helpers ----------------
__device__ __forceinline__ uint32_t smem_u32(const void* p) {
    uint32_t a;
    asm("{ .reg .u64 t; cvta.to.shared.u64 t, %1; cvt.u32.u64 %0, t; }"
        : "=r"(a) : "l"(p));
    return a;
}

__device__ __forceinline__ void ldsm_x4(uint32_t* r, uint32_t addr) {
    asm volatile("ldmatrix.sync.aligned.m8n8.x4.shared.b16 {%0,%1,%2,%3}, [%4];\n"
                 : "=r"(r[0]), "=r"(r[1]), "=r"(r[2]), "=r"(r[3]) : "r"(addr));
}

__device__ __forceinline__ void mma_f16(float* c, const uint32_t* a,
                                        uint32_t b0, uint32_t b1) {
    asm volatile(
        "mma.sync.aligned.m16n8k16.row.col.f32.f16.f16.f32 "
        "{%0,%1,%2,%3}, {%4,%5,%6,%7}, {%8,%9}, {%0,%1,%2,%3};\n"
        : "+f"(c[0]), "+f"(c[1]), "+f"(c[2]), "+f"(c[3])
        : "r"(a[0]), "r"(a[1]), "r"(a[2]), "r"(a[3]), "r"(b0), "r"(b1));
}

// ---------------- prep: build B' image once ----------------
__global__ void prep_B(const float* __restrict__ w1) {
    int i = blockIdx.x * blockDim.x + threadIdx.x;   // over 256*128
    if (i >= 256 * 128) return;
    int nn = i >> 7;            // output col 0..255
    int k = i & 127;
    int cb = nn >> 7;
    int nloc = nn & 127;
    g_Bimg[(size_t)nn * KS2 + k] = __float2half_rn(w1[(cb * 128 + k) * 128 + nloc]);
}

// ---------------- GEMM (exact R9 winner): C[128][256] per CTA ----------------
__global__ __launch_bounds__(256, 2)
void gemm_mma(const float* __restrict__ Zp, const float* __restrict__ Zo,
              const float* __restrict__ b1, int n) {
    extern __shared__ __half smem[];
    __half* As = smem;                       // [128][KS2]
    __half* Bs[2] = { smem + 128 * KS2,      // [64][KS2] buf0
                      smem + 192 * KS2 };    // [64][KS2] buf1

    const int tid = threadIdx.x;
    const int lane = tid & 31;
    const int wid = tid >> 5;
    const int wm = wid & 3;
    const int wn = wid >> 2;

    const float* A = blockIdx.y ? Zo : Zp;
    __half* C = blockIdx.y ? g_O : g_P;
    const long rowBase = (long)blockIdx.x * 128;

    auto cpchunk = [&](int c, __half* dst) {
        const __half* src = g_Bimg + (size_t)c * 64 * KS2;
        uint32_t d = smem_u32(dst);
        for (int i = tid; i < 64 * KS2 / 8; i += 256)
            asm volatile("cp.async.cg.shared.global [%0], [%1], 16;\n"
                         :: "r"(d + i * 16), "l"(src + i * 8) : "memory");
    };

    cpchunk(0, Bs[0]);
    asm volatile("cp.async.commit_group;\n" ::: "memory");
    cpchunk(1, Bs[1]);
    asm volatile("cp.async.commit_group;\n" ::: "memory");

    {
        int row = tid >> 1;
        int half = tid & 1;
        long grow = rowBase + row;
        const float* ap = A + grow * HH + half * 64;
        __half* as = As + row * KS2 + half * 64;
        #pragma unroll
        for (int j = 0; j < 16; j++) {
            float4 v = (grow < n) ? reinterpret_cast<const float4*>(ap)[j]
                                  : make_float4(0.f, 0.f, 0.f, 0.f);
            __half2 h0 = __floats2half2_rn(v.x, v.y);
            __half2 h1 = __floats2half2_rn(v.z, v.w);
            uint2 hh;
            hh.x = *reinterpret_cast<uint32_t*>(&h0);
            hh.y = *reinterpret_cast<uint32_t*>(&h1);
            *reinterpret_cast<uint2*>(as + j * 4) = hh;
        }
    }

    asm volatile("cp.async.wait_group 1;\n" ::: "memory");
    __syncthreads();

    const uint32_t sbA = smem_u32(As);
    const uint32_t sbB[2] = { smem_u32(Bs[0]), smem_u32(Bs[1]) };
    uint32_t a_base[2], b_off[2];
    #pragma unroll
    for (int tm = 0; tm < 2; tm++)
        a_base[tm] = sbA + ((wm * 32 + tm * 16 + (lane & 15)) * KS2
                            + (lane >> 4) * 8) * 2;
    #pragma unroll
    for (int np = 0; np < 2; np++)
        b_off[np] = ((wn * 32 + np * 16 + ((lane >> 4) << 3) + (lane & 7)) * KS2
                      + ((lane >> 3) & 1) * 8) * 2;

    for (int c = 0; c < 4; c++) {
        const uint32_t bb = sbB[c & 1];
        float acc[2][4][4];
        #pragma unroll
        for (int tm = 0; tm < 2; tm++)
            #pragma unroll
            for (int tn = 0; tn < 4; tn++)
                #pragma unroll
                for (int q = 0; q < 4; q++) acc[tm][tn][q] = 0.f;

        #pragma unroll 2
        for (int ks = 0; ks < 8; ks++) {
            uint32_t a[2][4], b[2][4];
            #pragma unroll
            for (int tm = 0; tm < 2; tm++) ldsm_x4(a[tm], a_base[tm] + ks * 32);
            #pragma unroll
            for (int np = 0; np < 2; np++) ldsm_x4(b[np], bb + b_off[np] + ks * 32);
            #pragma unroll
            for (int tm = 0; tm < 2; tm++)
                #pragma unroll
                for (int tn = 0; tn < 4; tn++)
                    mma_f16(acc[tm][tn], a[tm],
                            b[tn >> 1][(tn & 1) * 2], b[tn >> 1][(tn & 1) * 2 + 1]);
        }

        __syncthreads();
        if (c + 2 < 4) {
            cpchunk(c + 2, Bs[c & 1]);
            asm volatile("cp.async.commit_group;\n" ::: "memory");
        }

        #pragma unroll
        for (int tm = 0; tm < 2; tm++) {
            long r0 = rowBase + wm * 32 + tm * 16 + (lane >> 2);
            long r1 = r0 + 8;
            int colBase = c * 64 + wn * 32 + (lane & 3) * 2;
            #pragma unroll
            for (int tn = 0; tn < 4; tn++) {
                int col = colBase + tn * 8;
                float bx = 0.f, by = 0.f;
                if (col >= 128) {
                    float2 bv = *reinterpret_cast<const float2*>(b1 + col - 128);
                    bx = bv.x; by = bv.y;
                }
                if (r0 < n) {
                    __half2 v = __floats2half2_rn(acc[tm][tn][0] + bx,
                                                  acc[tm][tn][1] + by);
                    *reinterpret_cast<__half2*>(C + r0 * 256 + col) = v;
                }
                if (r1 < n) {
                    __half2 v = __floats2half2_rn(acc[tm][tn][2] + bx,
                                                  acc[tm][tn][3] + by);
                    *reinterpret_cast<__half2*>(C + r1 * 256 + col) = v;
                }
            }
        }

        if (c == 2) {
            asm volatile("cp.async.wait_group 0;\n" ::: "memory");
        } else if (c < 2) {
            asm volatile("cp.async.wait_group 1;\n" ::: "memory");
        }
        __syncthreads();
    }
}

// ---------------- edge decode: cp.async pipelined, 4-edge batches ----------------
// Per warp: double-buffered 2KB batch slots in SMEM. Issue batch k+2 while
// computing batch k. Compute: one warp-contiguous LDS.128 per edge (512B),
// xor-16 shuffle pairs x with y, lane halves split the 8-col dot, 32-lane reduce.
__global__ void edge_pipe(const int* __restrict__ e1, const int* __restrict__ e2,
                          const int* __restrict__ e3,
                          const float* __restrict__ w2, const float* __restrict__ b2,
                          float* __restrict__ out, int E) {
    __shared__ __align__(16) __half sm[8][2][4 * 256];   // [warp][buf][4 edges x 256 halfs]
    const int tid = threadIdx.x;
    const int warp = tid >> 5;
    const int lane = tid & 31;
    const int c16 = lane & 15;
    const bool isx = lane < 16;

    const int gw = blockIdx.x * 8 + warp;
    const int nw = gridDim.x * 8;
    const int nbatch = (3 * E) >> 2;     // E divisible by 4

    uint32_t bufu[2] = { smem_u32(&sm[warp][0][0]), smem_u32(&sm[warp][1][0]) };
    __half* bufp[2] = { &sm[warp][0][0], &sm[warp][1][0] };

    // per-lane weight slice: cols 8*(lane&15) + (lane<16 ? 0 : 4) .. +3
    const float4 w4 = *reinterpret_cast<const float4*>(w2 + 8 * c16 + (isx ? 0 : 4));
    const float bias = __ldg(b2);
    const __half2 z2 = __float2half2_rn(0.f);

    auto issue = [&](int b, int pbuf) {
        if (b < nbatch) {
            int e0 = b << 2;
            int t = (e0 >= 2 * E) ? 2 : (e0 >= E ? 1 : 0);
            int el = e0 - t * E;
            const int* idx = (t == 0) ? e1 : ((t == 1) ? e2 : e3);
            const __half* X = (t == 0) ? g_P : g_O;
            const __half* Y = ((t == 1) ? g_P : g_O) + 128;
            int4 s4 = *reinterpret_cast<const int4*>(idx + el);
            int4 d4 = *reinterpret_cast<const int4*>(idx + el + E);
            const int ss[4] = { s4.x, s4.y, s4.z, s4.w };
            const int dd[4] = { d4.x, d4.y, d4.z, d4.w };
            uint32_t dst0 = bufu[pbuf] + (isx ? 0 : 256) + c16 * 16;
            #pragma unroll
            for (int k = 0; k < 4; k++) {
                const __half* gp = isx ? (X + (size_t)ss[k] * 256 + c16 * 8)
                                       : (Y + (size_t)dd[k] * 256 + c16 * 8);
                asm volatile("cp.async.cg.shared.global [%0], [%1], 16;\n"
                             :: "r"(dst0 + k * 512), "l"(gp) : "memory");
            }
        }
        asm volatile("cp.async.commit_group;\n" ::: "memory");
    };

    issue(gw, 0);
    issue(gw + nw, 1);

    int parity = 0;
    for (int b = gw; b < nbatch; b += nw) {
        asm volatile("cp.async.wait_group 1;\n" ::: "memory");
        __syncwarp();

        const __half* buf = bufp[parity];
        int e0 = b << 2;
        #pragma unroll
        for (int k = 0; k < 4; k++) {
            // one contiguous 512B warp read: lane<16 -> x chunk lane, else y chunk lane-16
            uint4 v = *reinterpret_cast<const uint4*>(buf + k * 256 + lane * 8);
            uint4 w;
            w.x = __shfl_xor_sync(0xffffffffu, v.x, 16);
            w.y = __shfl_xor_sync(0xffffffffu, v.y, 16);
            w.z = __shfl_xor_sync(0xffffffffu, v.z, 16);
            w.w = __shfl_xor_sync(0xffffffffu, v.w, 16);
            const __half2* vv = reinterpret_cast<const __half2*>(&v);
            const __half2* ww = reinterpret_cast<const __half2*>(&w);
            int hi = isx ? 0 : 2;        // lane halves split the 8 columns
            __half2 r0 = __hmax2(__hadd2(vv[hi],     ww[hi]),     z2);
            __half2 r1 = __hmax2(__hadd2(vv[hi + 1], ww[hi + 1]), z2);
            float2 f0 = __half22float2(r0);
            float2 f1 = __half22float2(r1);
            float s = fmaf(f0.x, w4.x, fmaf(f0.y, w4.y,
                      fmaf(f1.x, w4.z, f1.y * w4.w)));
            #pragma unroll
            for (int o = 16; o > 0; o >>= 1)
                s += __shfl_xor_sync(0xffffffffu, s, o);
            if (lane == 0)
                out[e0 + k] = s + bias;
        }

        __syncwarp();
        issue(b + 2 * nw, parity);
        parity ^= 1;
    }
}

extern "C" void kernel_launch(void* const* d_in, const int* in_sizes, int n_in,
                              void* d_out, int out_size) {
    const float* z_p = (const float*)d_in[0];
    const float* z_o = (const float*)d_in[1];
    const int*   e1  = (const int*)d_in[2];   // ptnp:  pnode src, onode dst
    const int*   e2  = (const int*)d_in[3];   // nptp:  onode src, pnode dst
    const int*   e3  = (const int*)d_in[4];   // nptnp: onode src, onode dst
    const float* w1  = (const float*)d_in[5];
    const float* b1  = (const float*)d_in[6];
    const float* w2  = (const float*)d_in[7];
    const float* b2  = (const float*)d_in[8];
    float* out = (float*)d_out;

    const int n = in_sizes[0] / HH;       // 100000
    const int E = in_sizes[2] / 2;        // 500000
    (void)n_in; (void)out_size;

    const int smemBytes = (128 * KS2 + 2 * 64 * KS2) * 2;   // 69632 B
    cudaFuncSetAttribute(gemm_mma, cudaFuncAttributeMaxDynamicSharedMemorySize,
                         smemBytes);

    prep_B<<<(256 * 128 + 255) / 256, 256>>>(w1);

    dim3 g((n + 127) / 128, 2);
    gemm_mma<<<g, 256, smemBytes>>>(z_p, z_o, b1, n);

    // persistent-style grid: 6 CTAs/SM x 148 SMs (smem 32KB/CTA), warps loop
    edge_pipe<<<888, 256>>>(e1, e2, e3, w2, b2, out, E);
}

// round 15
// speedup vs baseline: 1.9338x; 1.9338x over previous
#include <cuda_runtime.h>
#include <cuda_fp16.h>
#include <cstdint>

#define NMAX 100000
#define HH   128
#define KS2  136          // padded row stride (half elems) for K=128 tiles

// Per-node projections (fp16). [node][256]: cols 0..127 = z@W1a (left/src),
// cols 128..255 = z@W1b + b1 (right/dst, bias folded).
__device__ __half g_P[(size_t)NMAX * 256];
__device__ __half g_O[(size_t)NMAX * 256];

// Pre-built B' image: [n(256 output cols)][KS2] fp16 (w1 transposed, fp16).
__device__ __align__(16) __half g_Bimg[256 * KS2];

// ---------------- helpers ----------------
__device__ __forceinline__ uint32_t smem_u32(const void* p) {
    uint32_t a;
    asm("{ .reg .u64 t; cvta.to.shared.u64 t, %1; cvt.u32.u64 %0, t; }"
        : "=r"(a) : "l"(p));
    return a;
}

__device__ __forceinline__ void ldsm_x4(uint32_t* r, uint32_t addr) {
    asm volatile("ldmatrix.sync.aligned.m8n8.x4.shared.b16 {%0,%1,%2,%3}, [%4];\n"
                 : "=r"(r[0]), "=r"(r[1]), "=r"(r[2]), "=r"(r[3]) : "r"(addr));
}

__device__ __forceinline__ void mma_f16(float* c, const uint32_t* a,
                                        uint32_t b0, uint32_t b1) {
    asm volatile(
        "mma.sync.aligned.m16n8k16.row.col.f32.f16.f16.f32 "
        "{%0,%1,%2,%3}, {%4,%5,%6,%7}, {%8,%9}, {%0,%1,%2,%3};\n"
        : "+f"(c[0]), "+f"(c[1]), "+f"(c[2]), "+f"(c[3])
        : "r"(a[0]), "r"(a[1]), "r"(a[2]), "r"(a[3]), "r"(b0), "r"(b1));
}

// 32B gather load, pinned in L2 (evict_last requires v8.b32 on this ptxas)
__device__ __forceinline__ void ldg_el8(const void* p, uint4& a, uint4& b) {
    asm volatile(
        "ld.global.nc.L2::evict_last.v8.b32 {%0,%1,%2,%3,%4,%5,%6,%7}, [%8];"
        : "=r"(a.x), "=r"(a.y), "=r"(a.z), "=r"(a.w),
          "=r"(b.x), "=r"(b.y), "=r"(b.z), "=r"(b.w)
        : "l"(p));
}

// ---------------- prep: build B' image once (coalesced w1 reads) ----------------
__global__ void prep_B(const float* __restrict__ w1) {
    int i = blockIdx.x * blockDim.x + threadIdx.x;   // over 256*128
    if (i >= 256 * 128) return;
    int nloc = i & 127;          // consecutive threads -> consecutive w1 elems
    int kk = (i >> 7) & 127;     // row of w1 within half
    int cb = i >> 14;            // which stacked half of w1
    int nn = cb * 128 + nloc;    // output col 0..255
    g_Bimg[(size_t)nn * KS2 + kk] = __float2half_rn(w1[(cb * 128 + kk) * 128 + nloc]);
}

// ---------------- GEMM: C[128 rows][256 cols] per CTA via mma.sync ----------------
// grid = (ceil(n/128), 2 matrices), 256 threads. K=128 fp16 direct.
// B streamed in 4 chunks of 64 cols, double-buffered cp.async. Occupancy 3.
__global__ __launch_bounds__(256, 3)
void gemm_mma(const float* __restrict__ Zp, const float* __restrict__ Zo,
              const float* __restrict__ b1, int n) {
    extern __shared__ __half smem[];
    __half* As = smem;                       // [128][KS2]
    __half* Bs[2] = { smem + 128 * KS2,      // [64][KS2] buf0
                      smem + 192 * KS2 };    // [64][KS2] buf1

    const int tid = threadIdx.x;
    const int lane = tid & 31;
    const int wid = tid >> 5;
    const int wm = wid & 3;          // 4 warps over M (32 rows)
    const int wn = wid >> 2;         // 2 warps over 32-col halves of chunk

    const float* A = blockIdx.y ? Zo : Zp;
    __half* C = blockIdx.y ? g_O : g_P;
    const long rowBase = (long)blockIdx.x * 128;

    auto cpchunk = [&](int c, __half* dst) {
        const __half* src = g_Bimg + (size_t)c * 64 * KS2;
        uint32_t d = smem_u32(dst);
        for (int i = tid; i < 64 * KS2 / 8; i += 256)
            asm volatile("cp.async.cg.shared.global [%0], [%1], 16;\n"
                         :: "r"(d + i * 16), "l"(src + i * 8) : "memory");
    };

    cpchunk(0, Bs[0]);
    asm volatile("cp.async.commit_group;\n" ::: "memory");
    cpchunk(1, Bs[1]);
    asm volatile("cp.async.commit_group;\n" ::: "memory");

    // ---- load A tile (128 rows x 128 fp32) -> fp16 ----
    {
        int row = tid >> 1;
        int half = tid & 1;                          // cols [half*64, half*64+64)
        long grow = rowBase + row;
        const float* ap = A + grow * HH + half * 64;
        __half* as = As + row * KS2 + half * 64;
        #pragma unroll
        for (int j = 0; j < 16; j++) {
            float4 v = (grow < n) ? reinterpret_cast<const float4*>(ap)[j]
                                  : make_float4(0.f, 0.f, 0.f, 0.f);
            __half2 h0 = __floats2half2_rn(v.x, v.y);
            __half2 h1 = __floats2half2_rn(v.z, v.w);
            uint2 hh;
            hh.x = *reinterpret_cast<uint32_t*>(&h0);
            hh.y = *reinterpret_cast<uint32_t*>(&h1);
            *reinterpret_cast<uint2*>(as + j * 4) = hh;
        }
    }

    asm volatile("cp.async.wait_group 1;\n" ::: "memory");
    __syncthreads();

    const uint32_t sbA = smem_u32(As);
    const uint32_t sbB[2] = { smem_u32(Bs[0]), smem_u32(Bs[1]) };
    uint32_t a_base[2], b_off[2];
    #pragma unroll
    for (int tm = 0; tm < 2; tm++)
        a_base[tm] = sbA + ((wm * 32 + tm * 16 + (lane & 15)) * KS2
                            + (lane >> 4) * 8) * 2;
    #pragma unroll
    for (int np = 0; np < 2; np++)
        b_off[np] = ((wn * 32 + np * 16 + ((lane >> 4) << 3) + (lane & 7)) * KS2
                      + ((lane >> 3) & 1) * 8) * 2;

    for (int c = 0; c < 4; c++) {
        const uint32_t bb = sbB[c & 1];
        float acc[2][4][4];
        #pragma unroll
        for (int tm = 0; tm < 2; tm++)
            #pragma unroll
            for (int tn = 0; tn < 4; tn++)
                #pragma unroll
                for (int q = 0; q < 4; q++) acc[tm][tn][q] = 0.f;

        #pragma unroll 2
        for (int ks = 0; ks < 8; ks++) {
            uint32_t a[2][4], b[2][4];
            #pragma unroll
            for (int tm = 0; tm < 2; tm++) ldsm_x4(a[tm], a_base[tm] + ks * 32);
            #pragma unroll
            for (int np = 0; np < 2; np++) ldsm_x4(b[np], bb + b_off[np] + ks * 32);
            #pragma unroll
            for (int tm = 0; tm < 2; tm++)
                #pragma unroll
                for (int tn = 0; tn < 4; tn++)
                    mma_f16(acc[tm][tn], a[tm],
                            b[tn >> 1][(tn & 1) * 2], b[tn >> 1][(tn & 1) * 2 + 1]);
        }

        __syncthreads();   // everyone done reading this buffer
        if (c + 2 < 4) {
            cpchunk(c + 2, Bs[c & 1]);
            asm volatile("cp.async.commit_group;\n" ::: "memory");
        }

        // ---- epilogue: fp32 acc (+b1 on right half) -> fp16 C ----
        #pragma unroll
        for (int tm = 0; tm < 2; tm++) {
            long r0 = rowBase + wm * 32 + tm * 16 + (lane >> 2);
            long r1 = r0 + 8;
            int colBase = c * 64 + wn * 32 + (lane & 3) * 2;
            #pragma unroll
            for (int tn = 0; tn < 4; tn++) {
                int col = colBase + tn * 8;
                float bx = 0.f, by = 0.f;
                if (col >= 128) {                       // right half: fold b1
                    float2 bv = *reinterpret_cast<const float2*>(b1 + col - 128);
                    bx = bv.x; by = bv.y;
                }
                if (r0 < n) {
                    __half2 v = __floats2half2_rn(acc[tm][tn][0] + bx,
                                                  acc[tm][tn][1] + by);
                    *reinterpret_cast<__half2*>(C + r0 * 256 + col) = v;
                }
                if (r1 < n) {
                    __half2 v = __floats2half2_rn(acc[tm][tn][2] + bx,
                                                  acc[tm][tn][3] + by);
                    *reinterpret_cast<__half2*>(C + r1 * 256 + col) = v;
                }
            }
        }

        if (c == 2) {
            asm volatile("cp.async.wait_group 0;\n" ::: "memory");
        } else if (c < 2) {
            asm volatile("cp.async.wait_group 1;\n" ::: "memory");
        }
        __syncthreads();
    }
}

// ---------------- edge decode (EXACT R9 winner): 8 lanes/edge, 2 edges/group ----------------
__global__ void edge_all(const int* __restrict__ e1, const int* __restrict__ e2,
                         const int* __restrict__ e3,
                         const float* __restrict__ w2, const float* __restrict__ b2,
                         float* __restrict__ out, int E) {
    const int tid = threadIdx.x;
    const int l = tid & 7;
    long g = (((long)blockIdx.x << 8) + tid) >> 3;   // lane-group id
    long eA = 2 * g;
    long eB = eA + 1;
    const long TE = 3L * E;
    if (eA >= TE) return;                            // TE even -> eB valid too

    // resolve edge A
    int tA = (eA >= 2L * E) ? 2 : (eA >= (long)E ? 1 : 0);
    int lA = (int)(eA - (long)tA * E);
    const int* iA = (tA == 0) ? e1 : ((tA == 1) ? e2 : e3);
    const __half* XA = (tA == 0) ? g_P : g_O;
    const __half* YA = ((tA == 1) ? g_P : g_O) + 128;
    // resolve edge B
    int tB = (eB >= 2L * E) ? 2 : (eB >= (long)E ? 1 : 0);
    int lB = (int)(eB - (long)tB * E);
    const int* iB = (tB == 0) ? e1 : ((tB == 1) ? e2 : e3);
    const __half* XB = (tB == 0) ? g_P : g_O;
    const __half* YB = ((tB == 1) ? g_P : g_O) + 128;

    int sA = iA[lA], dA = iA[lA + E];
    int sB = iB[lB], dB = iB[lB + E];

    const __half* xrA = XA + (size_t)sA * 256 + l * 16;
    const __half* yrA = YA + (size_t)dA * 256 + l * 16;
    const __half* xrB = XB + (size_t)sB * 256 + l * 16;
    const __half* yrB = YB + (size_t)dB * 256 + l * 16;

    // 4 independent 32B gathers in flight
    uint4 xa0, xa1, ya0, ya1, xb0, xb1, yb0, yb1;
    ldg_el8(xrA, xa0, xa1);
    ldg_el8(yrA, ya0, ya1);
    ldg_el8(xrB, xb0, xb1);
    ldg_el8(yrB, yb0, yb1);

    float2 w2v[8];
    #pragma unroll
    for (int j = 0; j < 4; j++) {
        float4 wv = reinterpret_cast<const float4*>(w2 + l * 16)[j];
        w2v[2 * j]     = make_float2(wv.x, wv.y);
        w2v[2 * j + 1] = make_float2(wv.z, wv.w);
    }
    const __half2 z2 = __float2half2_rn(0.f);

    const __half2* hxA0 = reinterpret_cast<const __half2*>(&xa0);
    const __half2* hxA1 = reinterpret_cast<const __half2*>(&xa1);
    const __half2* hyA0 = reinterpret_cast<const __half2*>(&ya0);
    const __half2* hyA1 = reinterpret_cast<const __half2*>(&ya1);
    const __half2* hxB0 = reinterpret_cast<const __half2*>(&xb0);
    const __half2* hxB1 = reinterpret_cast<const __half2*>(&xb1);
    const __half2* hyB0 = reinterpret_cast<const __half2*>(&yb0);
    const __half2* hyB1 = reinterpret_cast<const __half2*>(&yb1);

    float sumA = 0.f, sumB = 0.f;
    #pragma unroll
    for (int p = 0; p < 8; p++) {
        __half2 xA = (p < 4) ? hxA0[p] : hxA1[p - 4];
        __half2 yA = (p < 4) ? hyA0[p] : hyA1[p - 4];
        __half2 xB = (p < 4) ? hxB0[p] : hxB1[p - 4];
        __half2 yB = (p < 4) ? hyB0[p] : hyB1[p - 4];
        float2 rA = __half22float2(__hmax2(__hadd2(xA, yA), z2));
        float2 rB = __half22float2(__hmax2(__hadd2(xB, yB), z2));
        sumA = fmaf(rA.x, w2v[p].x, sumA);
        sumA = fmaf(rA.y, w2v[p].y, sumA);
        sumB = fmaf(rB.x, w2v[p].x, sumB);
        sumB = fmaf(rB.y, w2v[p].y, sumB);
    }

    #pragma unroll
    for (int o = 4; o > 0; o >>= 1) {
        sumA += __shfl_xor_sync(0xffffffffu, sumA, o);
        sumB += __shfl_xor_sync(0xffffffffu, sumB, o);
    }

    float bias = __ldg(b2);
    if (l == 0) out[eA] = sumA + bias;
    if (l == 1) out[eB] = sumB + bias;
}

extern "C" void kernel_launch(void* const* d_in, const int* in_sizes, int n_in,
                              void* d_out, int out_size) {
    const float* z_p = (const float*)d_in[0];
    const float* z_o = (const float*)d_in[1];
    const int*   e1  = (const int*)d_in[2];   // ptnp:  pnode src, onode dst
    const int*   e2  = (const int*)d_in[3];   // nptp:  onode src, pnode dst
    const int*   e3  = (const int*)d_in[4];   // nptnp: onode src, onode dst
    const float* w1  = (const float*)d_in[5];
    const float* b1  = (const float*)d_in[6];
    const float* w2  = (const float*)d_in[7];
    const float* b2  = (const float*)d_in[8];
    float* out = (float*)d_out;

    const int n = in_sizes[0] / HH;       // 100000
    const int E = in_sizes[2] / 2;        // 500000
    (void)n_in; (void)out_size;

    const int smemBytes = (128 * KS2 + 2 * 64 * KS2) * 2;   // 69632 B
    cudaFuncSetAttribute(gemm_mma, cudaFuncAttributeMaxDynamicSharedMemorySize,
                         smemBytes);

    prep_B<<<(256 * 128 + 255) / 256, 256>>>(w1);

    dim3 g((n + 127) / 128, 2);
    gemm_mma<<<g, 256, smemBytes>>>(z_p, z_o, b1, n);

    long totalE = 3L * E;                          // even
    long groups = (totalE + 1) / 2;                // 2 edges per 8-lane group
    int blocks = (int)((groups * 8 + 255) / 256);
    edge_all<<<blocks, 256>>>(e1, e2, e3, w2, b2, out, E);
}

// round 16
// speedup vs baseline: 2.0330x; 1.0513x over previous
#include <cuda_runtime.h>
#include <cuda_fp16.h>
#include <cstdint>

#define NMAX 100000
#define HH   128
#define KS2  136          // padded row stride (half elems) for K=128 tiles

// Per-node projections (fp16). [node][256]: cols 0..127 = z@W1a (left/src),
// cols 128..255 = z@W1b + b1 (right/dst, bias folded).
__device__ __half g_P[(size_t)NMAX * 256];
__device__ __half g_O[(size_t)NMAX * 256];

// Pre-built B' image: [n(256 output cols)][KS2] fp16 (w1 transposed, fp16).
__device__ __align__(16) __half g_Bimg[256 * KS2];

// ---------------- helpers ----------------
__device__ __forceinline__ uint32_t smem_u32(const void* p) {
    uint32_t a;
    asm("{ .reg .u64 t; cvta.to.shared.u64 t, %1; cvt.u32.u64 %0, t; }"
        : "=r"(a) : "l"(p));
    return a;
}

__device__ __forceinline__ void ldsm_x4(uint32_t* r, uint32_t addr) {
    asm volatile("ldmatrix.sync.aligned.m8n8.x4.shared.b16 {%0,%1,%2,%3}, [%4];\n"
                 : "=r"(r[0]), "=r"(r[1]), "=r"(r[2]), "=r"(r[3]) : "r"(addr));
}

__device__ __forceinline__ void mma_f16(float* c, const uint32_t* a,
                                        uint32_t b0, uint32_t b1) {
    asm volatile(
        "mma.sync.aligned.m16n8k16.row.col.f32.f16.f16.f32 "
        "{%0,%1,%2,%3}, {%4,%5,%6,%7}, {%8,%9}, {%0,%1,%2,%3};\n"
        : "+f"(c[0]), "+f"(c[1]), "+f"(c[2]), "+f"(c[3])
        : "r"(a[0]), "r"(a[1]), "r"(a[2]), "r"(a[3]), "r"(b0), "r"(b1));
}

// 32B gather load, pinned in L2 (evict_last requires v8.b32 on this ptxas)
__device__ __forceinline__ void ldg_el8(const void* p, uint4& a, uint4& b) {
    asm volatile(
        "ld.global.nc.L2::evict_last.v8.b32 {%0,%1,%2,%3,%4,%5,%6,%7}, [%8];"
        : "=r"(a.x), "=r"(a.y), "=r"(a.z), "=r"(a.w),
          "=r"(b.x), "=r"(b.y), "=r"(b.z), "=r"(b.w)
        : "l"(p));
}

// ---------------- prep: build B' image once ----------------
__global__ void prep_B(const float* __restrict__ w1) {
    int i = blockIdx.x * blockDim.x + threadIdx.x;   // over 256*128
    if (i >= 256 * 128) return;
    int nn = i >> 7;            // output col 0..255
    int k = i & 127;
    int cb = nn >> 7;
    int nloc = nn & 127;
    g_Bimg[(size_t)nn * KS2 + k] = __float2half_rn(w1[(cb * 128 + k) * 128 + nloc]);
}

// ---------------- GEMM: C[128 rows][256 cols] per CTA via mma.sync ----------------
// grid = (ceil(n/128), 2 matrices), 256 threads. K=128 fp16 direct.
// B streamed in 4 chunks of 64 cols, double-buffered cp.async.
__global__ __launch_bounds__(256, 2)
void gemm_mma(const float* __restrict__ Zp, const float* __restrict__ Zo,
              const float* __restrict__ b1, int n) {
    extern __shared__ __half smem[];
    __half* As = smem;                       // [128][KS2]
    __half* Bs[2] = { smem + 128 * KS2,      // [64][KS2] buf0
                      smem + 192 * KS2 };    // [64][KS2] buf1

    const int tid = threadIdx.x;
    const int lane = tid & 31;
    const int wid = tid >> 5;
    const int wm = wid & 3;          // 4 warps over M (32 rows)
    const int wn = wid >> 2;         // 2 warps over 32-col halves of chunk

    const float* A = blockIdx.y ? Zo : Zp;
    __half* C = blockIdx.y ? g_O : g_P;
    const long rowBase = (long)blockIdx.x * 128;

    auto cpchunk = [&](int c, __half* dst) {
        const __half* src = g_Bimg + (size_t)c * 64 * KS2;
        uint32_t d = smem_u32(dst);
        for (int i = tid; i < 64 * KS2 / 8; i += 256)
            asm volatile("cp.async.cg.shared.global [%0], [%1], 16;\n"
                         :: "r"(d + i * 16), "l"(src + i * 8) : "memory");
    };

    cpchunk(0, Bs[0]);
    asm volatile("cp.async.commit_group;\n" ::: "memory");
    cpchunk(1, Bs[1]);
    asm volatile("cp.async.commit_group;\n" ::: "memory");

    // ---- load A tile (128 rows x 128 fp32) -> fp16 ----
    {
        int row = tid >> 1;
        int half = tid & 1;                          // cols [half*64, half*64+64)
        long grow = rowBase + row;
        const float* ap = A + grow * HH + half * 64;
        __half* as = As + row * KS2 + half * 64;
        #pragma unroll
        for (int j = 0; j < 16; j++) {
            float4 v = (grow < n) ? reinterpret_cast<const float4*>(ap)[j]
                                  : make_float4(0.f, 0.f, 0.f, 0.f);
            __half2 h0 = __floats2half2_rn(v.x, v.y);
            __half2 h1 = __floats2half2_rn(v.z, v.w);
            uint2 hh;
            hh.x = *reinterpret_cast<uint32_t*>(&h0);
            hh.y = *reinterpret_cast<uint32_t*>(&h1);
            *reinterpret_cast<uint2*>(as + j * 4) = hh;
        }
    }

    asm volatile("cp.async.wait_group 1;\n" ::: "memory");
    __syncthreads();

    const uint32_t sbA = smem_u32(As);
    const uint32_t sbB[2] = { smem_u32(Bs[0]), smem_u32(Bs[1]) };
    uint32_t a_base[2], b_off[2];
    #pragma unroll
    for (int tm = 0; tm < 2; tm++)
        a_base[tm] = sbA + ((wm * 32 + tm * 16 + (lane & 15)) * KS2
                            + (lane >> 4) * 8) * 2;
    #pragma unroll
    for (int np = 0; np < 2; np++)
        b_off[np] = ((wn * 32 + np * 16 + ((lane >> 4) << 3) + (lane & 7)) * KS2
                      + ((lane >> 3) & 1) * 8) * 2;

    for (int c = 0; c < 4; c++) {
        const uint32_t bb = sbB[c & 1];
        float acc[2][4][4];
        #pragma unroll
        for (int tm = 0; tm < 2; tm++)
            #pragma unroll
            for (int tn = 0; tn < 4; tn++)
                #pragma unroll
                for (int q = 0; q < 4; q++) acc[tm][tn][q] = 0.f;

        #pragma unroll 2
        for (int ks = 0; ks < 8; ks++) {
            uint32_t a[2][4], b[2][4];
            #pragma unroll
            for (int tm = 0; tm < 2; tm++) ldsm_x4(a[tm], a_base[tm] + ks * 32);
            #pragma unroll
            for (int np = 0; np < 2; np++) ldsm_x4(b[np], bb + b_off[np] + ks * 32);
            #pragma unroll
            for (int tm = 0; tm < 2; tm++)
                #pragma unroll
                for (int tn = 0; tn < 4; tn++)
                    mma_f16(acc[tm][tn], a[tm],
                            b[tn >> 1][(tn & 1) * 2], b[tn >> 1][(tn & 1) * 2 + 1]);
        }

        __syncthreads();   // everyone done reading this buffer
        if (c + 2 < 4) {
            cpchunk(c + 2, Bs[c & 1]);
            asm volatile("cp.async.commit_group;\n" ::: "memory");
        }

        // ---- epilogue: fp32 acc (+b1 on right half) -> fp16 C ----
        #pragma unroll
        for (int tm = 0; tm < 2; tm++) {
            long r0 = rowBase + wm * 32 + tm * 16 + (lane >> 2);
            long r1 = r0 + 8;
            int colBase = c * 64 + wn * 32 + (lane & 3) * 2;
            #pragma unroll
            for (int tn = 0; tn < 4; tn++) {
                int col = colBase + tn * 8;
                float bx = 0.f, by = 0.f;
                if (col >= 128) {                       // right half: fold b1
                    float2 bv = *reinterpret_cast<const float2*>(b1 + col - 128);
                    bx = bv.x; by = bv.y;
                }
                if (r0 < n) {
                    __half2 v = __floats2half2_rn(acc[tm][tn][0] + bx,
                                                  acc[tm][tn][1] + by);
                    *reinterpret_cast<__half2*>(C + r0 * 256 + col) = v;
                }
                if (r1 < n) {
                    __half2 v = __floats2half2_rn(acc[tm][tn][2] + bx,
                                                  acc[tm][tn][3] + by);
                    *reinterpret_cast<__half2*>(C + r1 * 256 + col) = v;
                }
            }
        }

        if (c == 2) {
            asm volatile("cp.async.wait_group 0;\n" ::: "memory");
        } else if (c < 2) {
            asm volatile("cp.async.wait_group 1;\n" ::: "memory");
        }
        __syncthreads();
    }
}

// ---------------- edge decode: 8 lanes per edge, 2 edges per lane-group ----------------
__global__ void edge_all(const int* __restrict__ e1, const int* __restrict__ e2,
                         const int* __restrict__ e3,
                         const float* __restrict__ w2, const float* __restrict__ b2,
                         float* __restrict__ out, int E) {
    const int tid = threadIdx.x;
    const int l = tid & 7;
    long g = (((long)blockIdx.x << 8) + tid) >> 3;   // lane-group id
    long eA = 2 * g;
    long eB = eA + 1;
    const long TE = 3L * E;
    if (eA >= TE) return;                            // TE even -> eB valid too

    // resolve edge A
    int tA = (eA >= 2L * E) ? 2 : (eA >= (long)E ? 1 : 0);
    int lA = (int)(eA - (long)tA * E);
    const int* iA = (tA == 0) ? e1 : ((tA == 1) ? e2 : e3);
    const __half* XA = (tA == 0) ? g_P : g_O;
    const __half* YA = ((tA == 1) ? g_P : g_O) + 128;
    // resolve edge B
    int tB = (eB >= 2L * E) ? 2 : (eB >= (long)E ? 1 : 0);
    int lB = (int)(eB - (long)tB * E);
    const int* iB = (tB == 0) ? e1 : ((tB == 1) ? e2 : e3);
    const __half* XB = (tB == 0) ? g_P : g_O;
    const __half* YB = ((tB == 1) ? g_P : g_O) + 128;

    int sA = iA[lA], dA = iA[lA + E];
    int sB = iB[lB], dB = iB[lB + E];

    const __half* xrA = XA + (size_t)sA * 256 + l * 16;
    const __half* yrA = YA + (size_t)dA * 256 + l * 16;
    const __half* xrB = XB + (size_t)sB * 256 + l * 16;
    const __half* yrB = YB + (size_t)dB * 256 + l * 16;

    // 4 independent 32B gathers in flight
    uint4 xa0, xa1, ya0, ya1, xb0, xb1, yb0, yb1;
    ldg_el8(xrA, xa0, xa1);
    ldg_el8(yrA, ya0, ya1);
    ldg_el8(xrB, xb0, xb1);
    ldg_el8(yrB, yb0, yb1);

    float2 w2v[8];
    #pragma unroll
    for (int j = 0; j < 4; j++) {
        float4 wv = reinterpret_cast<const float4*>(w2 + l * 16)[j];
        w2v[2 * j]     = make_float2(wv.x, wv.y);
        w2v[2 * j + 1] = make_float2(wv.z, wv.w);
    }
    const __half2 z2 = __float2half2_rn(0.f);

    const __half2* hxA0 = reinterpret_cast<const __half2*>(&xa0);
    const __half2* hxA1 = reinterpret_cast<const __half2*>(&xa1);
    const __half2* hyA0 = reinterpret_cast<const __half2*>(&ya0);
    const __half2* hyA1 = reinterpret_cast<const __half2*>(&ya1);
    const __half2* hxB0 = reinterpret_cast<const __half2*>(&xb0);
    const __half2* hxB1 = reinterpret_cast<const __half2*>(&xb1);
    const __half2* hyB0 = reinterpret_cast<const __half2*>(&yb0);
    const __half2* hyB1 = reinterpret_cast<const __half2*>(&yb1);

    float sumA = 0.f, sumB = 0.f;
    #pragma unroll
    for (int p = 0; p < 8; p++) {
        __half2 xA = (p < 4) ? hxA0[p] : hxA1[p - 4];
        __half2 yA = (p < 4) ? hyA0[p] : hyA1[p - 4];
        __half2 xB = (p < 4) ? hxB0[p] : hxB1[p - 4];
        __half2 yB = (p < 4) ? hyB0[p] : hyB1[p - 4];
        float2 rA = __half22float2(__hmax2(__hadd2(xA, yA), z2));
        float2 rB = __half22float2(__hmax2(__hadd2(xB, yB), z2));
        sumA = fmaf(rA.x, w2v[p].x, sumA);
        sumA = fmaf(rA.y, w2v[p].y, sumA);
        sumB = fmaf(rB.x, w2v[p].x, sumB);
        sumB = fmaf(rB.y, w2v[p].y, sumB);
    }

    #pragma unroll
    for (int o = 4; o > 0; o >>= 1) {
        sumA += __shfl_xor_sync(0xffffffffu, sumA, o);
        sumB += __shfl_xor_sync(0xffffffffu, sumB, o);
    }

    float bias = __ldg(b2);
    if (l == 0) out[eA] = sumA + bias;
    if (l == 1) out[eB] = sumB + bias;
}

extern "C" void kernel_launch(void* const* d_in, const int* in_sizes, int n_in,
                              void* d_out, int out_size) {
    const float* z_p = (const float*)d_in[0];
    const float* z_o = (const float*)d_in[1];
    const int*   e1  = (const int*)d_in[2];   // ptnp:  pnode src, onode dst
    const int*   e2  = (const int*)d_in[3];   // nptp:  onode src, pnode dst
    const int*   e3  = (const int*)d_in[4];   // nptnp: onode src, onode dst
    const float* w1  = (const float*)d_in[5];
    const float* b1  = (const float*)d_in[6];
    const float* w2  = (const float*)d_in[7];
    const float* b2  = (const float*)d_in[8];
    float* out = (float*)d_out;

    const int n = in_sizes[0] / HH;       // 100000
    const int E = in_sizes[2] / 2;        // 500000
    (void)n_in; (void)out_size;

    const int smemBytes = (128 * KS2 + 2 * 64 * KS2) * 2;   // 69632 B
    cudaFuncSetAttribute(gemm_mma, cudaFuncAttributeMaxDynamicSharedMemorySize,
                         smemBytes);

    prep_B<<<(256 * 128 + 255) / 256, 256>>>(w1);

    dim3 g((n + 127) / 128, 2);
    gemm_mma<<<g, 256, smemBytes>>>(z_p, z_o, b1, n);

    long totalE = 3L * E;                          // even
    long groups = (totalE + 1) / 2;                // 2 edges per 8-lane group
    int blocks = (int)((groups * 8 + 255) / 256);
    edge_all<<<blocks, 256>>>(e1, e2, e3, w2, b2, out, E);
}